// round 2
// baseline (speedup 1.0000x reference)
#include <cuda_runtime.h>

#define D_  48
#define H_  256
#define W_  256
#define DM_ 48
#define HM_ 128
#define WM_ 128
#define PH_ 4

__global__ void __launch_bounds__(256)
mvf_warp_kernel(const float* __restrict__ image,   // (D,H,W,2)
                const float* __restrict__ mvf,     // (PH,3,DM,HM,WM)
                float* __restrict__ out)           // (5,D,H,W,2)
{
    const int tid = threadIdx.x;
    const int y = blockIdx.x;      // 0..255
    const int z = blockIdx.y;      // 0..47
    const int p = blockIdx.z;      // 0..4 ; p==PH_ -> pure copy slice

    if (p == PH_) {
        // out[:,0] = image : copy one (z,y) row = 512 floats, coalesced float2
        const size_t off = ((size_t)z * H_ + y) * W_ * 2;
        const float2* src = reinterpret_cast<const float2*>(image + off);
        float2* dst = reinterpret_cast<float2*>(out + off);
        dst[tid] = src[tid];
        return;
    }

    // ---- stage y-interpolated mvf row into smem ----
    __shared__ float sm[3][WM_];

    // 2x upsample along y (jax.image.resize trilinear, edge-renormalized == clamp)
    float cy = 0.5f * (float)y - 0.25f;
    float fy = floorf(cy);
    int   jy0 = (int)fy;
    float wy1 = cy - fy;
    float wy0 = 1.0f - wy1;
    int   jy1 = jy0 + 1;
    if (jy0 < 0)       { jy0 = 0;       wy0 = 0.0f; wy1 = 1.0f; }
    if (jy1 > HM_ - 1) { jy1 = HM_ - 1; wy1 = 0.0f; wy0 = 1.0f; }

    const int plane = HM_ * WM_;
    {
        const int r0 = jy0 * WM_;
        const int r1 = jy1 * WM_;
        #pragma unroll
        for (int i = tid; i < 3 * WM_; i += 256) {
            int ch = i >> 7;
            int xs = i & (WM_ - 1);
            const float* s = mvf + ((size_t)(p * 3 + ch) * DM_ + z) * plane + xs;
            sm[ch][xs] = wy0 * s[r0] + wy1 * s[r1];
        }
    }
    __syncthreads();

    // ---- per-pixel: x-interp of mvf from smem ----
    const int x = tid;
    float cx = 0.5f * (float)x - 0.25f;
    float fx = floorf(cx);
    int   jx0 = (int)fx;
    float wx1 = cx - fx;
    float wx0 = 1.0f - wx1;
    int   jx1 = jx0 + 1;
    if (jx0 < 0)       { jx0 = 0;       wx0 = 0.0f; wx1 = 1.0f; }
    if (jx1 > WM_ - 1) { jx1 = WM_ - 1; wx1 = 0.0f; wx0 = 1.0f; }

    float m0 = wx0 * sm[0][jx0] + wx1 * sm[0][jx1];
    float m1 = wx0 * sm[1][jx0] + wx1 * sm[1][jx1];
    float m2 = wx0 * sm[2][jx0] + wx1 * sm[2][jx1];

    // absolute sample coords: scale (1,2,2) on (z,y,x)
    float zc = (float)z +        m0;
    float yc = (float)y + 2.0f * m1;
    float xc = (float)x + 2.0f * m2;

    float zf = floorf(zc), yf = floorf(yc), xf = floorf(xc);
    int z0 = (int)zf, y0 = (int)yf, x0 = (int)xf;
    float wz = zc - zf, wy = yc - yf, wx = xc - xf;
    float wzA = 1.0f - wz, wyA = 1.0f - wy, wxA = 1.0f - wx;

    float acc0 = 0.0f, acc1 = 0.0f;
    #pragma unroll
    for (int dz = 0; dz < 2; dz++) {
        int zi = z0 + dz;
        if ((unsigned)zi >= (unsigned)D_) continue;
        float wzc = dz ? wz : wzA;
        #pragma unroll
        for (int dy = 0; dy < 2; dy++) {
            int yi = y0 + dy;
            if ((unsigned)yi >= (unsigned)H_) continue;
            float wyc = wzc * (dy ? wy : wyA);
            int rowbase = (zi * H_ + yi) * W_;
            #pragma unroll
            for (int dx = 0; dx < 2; dx++) {
                int xi = x0 + dx;
                if ((unsigned)xi >= (unsigned)W_) continue;
                float w = wyc * (dx ? wx : wxA);
                float2 v = *reinterpret_cast<const float2*>(image + (size_t)(rowbase + xi) * 2);
                acc0 = fmaf(w, v.x, acc0);
                acc1 = fmaf(w, v.y, acc1);
            }
        }
    }

    // out[(1+p), z, y, x, :]
    size_t o = ((size_t)((1 + p) * D_ + z) * (H_ * W_) + (size_t)(y * W_ + x)) * 2;
    *reinterpret_cast<float2*>(out + o) = make_float2(acc0, acc1);
}

extern "C" void kernel_launch(void* const* d_in, const int* in_sizes, int n_in,
                              void* d_out, int out_size)
{
    const float* image = (const float*)d_in[0];   // (1,1,48,256,256,2) fp32
    const float* mvf   = (const float*)d_in[1];   // (1,4,3,48,128,128) fp32
    float* out = (float*)d_out;                   // (1,5,48,256,256,2) fp32

    dim3 grid(H_, D_, PH_ + 1);   // z-slice PH_ does the image copy
    mvf_warp_kernel<<<grid, 256>>>(image, mvf, out);
}